// round 6
// baseline (speedup 1.0000x reference)
#include <cuda_runtime.h>
#include <float.h>

#define B_  8
#define N_  4096
#define C_  128
#define OI_ 5
#define OS_ 13
#define K_  30

// ---- scratch (static device globals; no runtime allocation) ----
__device__ __align__(16) float g_epts[B_ * N_ * 8];            // [b][n][8]: e0..e4, sq, pad
__device__ __align__(16) float g_fsemT[(size_t)B_ * N_ * C_];  // [b][n][c]
__device__ int g_nnidx[B_ * N_ * K_];                          // [b][n][k]

// ============================================================================
// Kernel A: fused adaptation MLP + e_ins.
// e_ins[b,o,n] = b_ins[o] + sum_c W_ins[o,c] * (f_ins[b,c,n] +
//                relu(gamma[c]*(sum_s W_adapt[c,s]*f_sem[b,s,n] + b_adapt[c]) + beta[c]))
// One block = 128 columns of one batch. 8x8 register-tiled smem GEMM.
// ============================================================================
__global__ void __launch_bounds__(256, 1)
mlp_kernel(const float* __restrict__ f_sem, const float* __restrict__ f_ins,
           const float* __restrict__ W_adapt, const float* __restrict__ b_adapt,
           const float* __restrict__ gamma_a, const float* __restrict__ beta_a,
           const float* __restrict__ W_ins, const float* __restrict__ b_ins,
           float* __restrict__ e_out)
{
    extern __shared__ float sm[];
    float* sW   = sm;            // 16384: W_adapt[c][s]
    float* sX   = sm + 16384;    // 16384: f_sem[s][n] tile, then f_sins[c][n]
    float* sWi  = sX + 16384;    // 640:   W_ins[o][c]
    float* sPar = sWi + 640;     // 392:   b_adapt | gamma | beta | b_ins

    const int t  = threadIdx.x;
    const int b  = blockIdx.y;
    const int n0 = blockIdx.x * 128;

    {
        const float4* W4 = (const float4*)W_adapt;
        float4* sW4 = (float4*)sW;
        #pragma unroll
        for (int i = 0; i < 16; i++) sW4[t + 256 * i] = W4[t + 256 * i];
    }
    for (int i4 = t; i4 < 4096; i4 += 256) {
        int s = i4 >> 5, nn = (i4 & 31) * 4;
        ((float4*)sX)[i4] = *(const float4*)(f_sem + ((size_t)(b * C_ + s)) * N_ + n0 + nn);
    }
    if (t < 128) { sPar[t] = b_adapt[t]; sPar[128 + t] = gamma_a[t]; sPar[256 + t] = beta_a[t]; }
    else if (t < 133) sPar[384 + (t - 128)] = b_ins[t - 128];
    for (int i = t; i < 640; i += 256) sWi[i] = W_ins[i];
    __syncthreads();

    const int tx = t & 15, ty = t >> 4;
    const int c0 = ty * 8, nl = tx * 8;
    float acc[8][8];
    #pragma unroll
    for (int u = 0; u < 8; u++)
        #pragma unroll
        for (int v = 0; v < 8; v++) acc[u][v] = 0.f;

    for (int s = 0; s < 128; s++) {
        float a[8];
        #pragma unroll
        for (int u = 0; u < 8; u++) a[u] = sW[(c0 + u) * 128 + s];
        float4 p0 = *(float4*)(sX + s * 128 + nl);
        float4 p1 = *(float4*)(sX + s * 128 + nl + 4);
        float bb[8] = {p0.x, p0.y, p0.z, p0.w, p1.x, p1.y, p1.z, p1.w};
        #pragma unroll
        for (int u = 0; u < 8; u++)
            #pragma unroll
            for (int v = 0; v < 8; v++) acc[u][v] = fmaf(a[u], bb[v], acc[u][v]);
    }
    __syncthreads();  // all reads of sX done before overwrite

    #pragma unroll
    for (int u = 0; u < 8; u++) {
        int c = c0 + u;
        float ba = sPar[c], ga = sPar[128 + c], be = sPar[256 + c];
        const float* fip = f_ins + ((size_t)(b * C_ + c)) * N_ + n0 + nl;
        float4 f0 = *(const float4*)fip;
        float4 f1 = *(const float4*)(fip + 4);
        float fv[8] = {f0.x, f0.y, f0.z, f0.w, f1.x, f1.y, f1.z, f1.w};
        #pragma unroll
        for (int v = 0; v < 8; v++) {
            float val = fmaf(ga, acc[u][v] + ba, be);
            val = fmaxf(val, 0.f) + fv[v];
            sX[c * 128 + nl + v] = val;   // f_sins
        }
    }
    __syncthreads();

    if (t < 128) {
        int n = n0 + t;
        float a0 = sPar[384], a1 = sPar[385], a2 = sPar[386], a3 = sPar[387], a4 = sPar[388];
        for (int c = 0; c < 128; c++) {
            float f = sX[c * 128 + t];
            a0 = fmaf(sWi[c], f, a0);
            a1 = fmaf(sWi[128 + c], f, a1);
            a2 = fmaf(sWi[256 + c], f, a2);
            a3 = fmaf(sWi[384 + c], f, a3);
            a4 = fmaf(sWi[512 + c], f, a4);
        }
        // sq exactly as reference: per-element rounded square, sequential add.
        float s0 = __fmul_rn(a0, a0);
        float s1 = __fmul_rn(a1, a1);
        float s2 = __fmul_rn(a2, a2);
        float s3 = __fmul_rn(a3, a3);
        float s4 = __fmul_rn(a4, a4);
        float sq = __fadd_rn(__fadd_rn(__fadd_rn(__fadd_rn(s0, s1), s2), s3), s4);
        size_t ob = (size_t)b * OI_ * N_ + n;
        e_out[ob] = a0; e_out[ob + N_] = a1; e_out[ob + 2 * N_] = a2;
        e_out[ob + 3 * N_] = a3; e_out[ob + 4 * N_] = a4;
        float* ep = g_epts + ((size_t)b * N_ + n) * 8;
        ep[0] = a0; ep[1] = a1; ep[2] = a2; ep[3] = a3; ep[4] = a4;
        ep[5] = sq; ep[6] = 0.f; ep[7] = 0.f;
    }
}

// ============================================================================
// Kernel B: transpose f_sem [B,C,N] -> g_fsemT [B,N,C] for coalesced gathers.
// ============================================================================
__global__ void __launch_bounds__(256, 2)
transpose_kernel(const float* __restrict__ f_sem)
{
    __shared__ float tile[32][33];
    const int b = blockIdx.z, c0 = blockIdx.y * 32, x0 = blockIdx.x * 32;
    const int tx = threadIdx.x, ty = threadIdx.y;  // 32 x 8
    #pragma unroll
    for (int j = 0; j < 32; j += 8)
        tile[ty + j][tx] = f_sem[((size_t)(b * C_ + c0 + ty + j)) * N_ + x0 + tx];
    __syncthreads();
    #pragma unroll
    for (int j = 0; j < 32; j += 8)
        g_fsemT[((size_t)b * N_ + x0 + ty + j) * C_ + c0 + tx] = tile[tx][ty + j];
}

// ============================================================================
// Kernel C: exact 30-NN per query. Thread-per-query; all 4096 candidates of
// this batch resident in smem (stride-8 for vector loads); register top-30 by
// replace-max (first-match-only to survive duplicate distances). Distances
// evaluated with the reference's exact rounding order:
//   dot  = sequential fma over 5 dims (starting from a rounded mul)
//   dist = (sq_i - (2*dot)) + sq_j, no FMA contraction.
// Strict '<' reproduces jax top_k's lower-index tie preference.
// ============================================================================
__global__ void __launch_bounds__(256, 1)
knn_kernel()
{
    extern __shared__ float sc[];  // [4096][8]
    const int t = threadIdx.x, b = blockIdx.y;
    {
        const float4* eb = (const float4*)(g_epts + (size_t)b * N_ * 8);
        float4* s4 = (float4*)sc;
        #pragma unroll
        for (int i = 0; i < 32; i++) s4[t + 256 * i] = eb[t + 256 * i];
    }
    __syncthreads();

    const int q = blockIdx.x * 256 + t;
    const float* qq = sc + q * 8;
    const float e0 = qq[0], e1 = qq[1], e2 = qq[2], e3 = qq[3], e4 = qq[4];
    const float sqi = qq[5];

    float bd[K_];
    int   bi[K_];
    #pragma unroll
    for (int u = 0; u < K_; u++) { bd[u] = FLT_MAX; bi[u] = 0; }
    float worst = FLT_MAX;

    for (int j = 0; j < N_; j++) {
        const float* cj = sc + j * 8;
        float4 cv = *(const float4*)cj;
        float c4 = cj[4], sqj = cj[5];
        float dot = __fmul_rn(e0, cv.x);
        dot = __fmaf_rn(e1, cv.y, dot);
        dot = __fmaf_rn(e2, cv.z, dot);
        dot = __fmaf_rn(e3, cv.w, dot);
        dot = __fmaf_rn(e4, c4, dot);
        float d = __fadd_rn(__fsub_rn(sqi, __fmul_rn(2.0f, dot)), sqj);
        if (d < worst) {
            bool done = false;
            #pragma unroll
            for (int u = 0; u < K_; u++) {
                bool p = (!done) && (bd[u] == worst);
                bd[u] = p ? d : bd[u];
                bi[u] = p ? j : bi[u];
                done = done || p;
            }
            float w = bd[0];
            #pragma unroll
            for (int u = 1; u < K_; u++) w = fmaxf(w, bd[u]);
            worst = w;
        }
    }

    int* op = g_nnidx + ((size_t)b * N_ + q) * K_;
    #pragma unroll
    for (int u = 0; u < K_; u++) op[u] = bi[u];
}

// ============================================================================
// Kernel D: f_isem = max_k f_sem[:, nn_idx[n,k]]; p_sem = W_sem @ f_isem + b.
// Warp-per-point: each lane owns 4 channels via one float4 gather per neighbor
// (fully coalesced thanks to the transpose), then 13-way warp reduction.
// ============================================================================
__global__ void __launch_bounds__(256, 2)
gather_kernel(const float* __restrict__ W_sem, const float* __restrict__ b_sem,
              float* __restrict__ p_out)
{
    __shared__ __align__(16) float sW[OS_ * C_];
    __shared__ float sb[OS_];
    const int t = threadIdx.x, b = blockIdx.y;
    for (int i = t; i < OS_ * C_; i += 256) sW[i] = W_sem[i];
    if (t < OS_) sb[t] = b_sem[t];
    __syncthreads();

    const int w = t >> 5, lane = t & 31;
    const int n = blockIdx.x * 8 + w;
    const int* ip = g_nnidx + ((size_t)b * N_ + n) * K_;
    int myidx = (lane < K_) ? ip[lane] : 0;
    const float* base = g_fsemT + (size_t)b * N_ * C_;

    float4 m = make_float4(-3.0e38f, -3.0e38f, -3.0e38f, -3.0e38f);
    #pragma unroll
    for (int k = 0; k < K_; k++) {
        int j = __shfl_sync(0xffffffffu, myidx, k);
        float4 v = *(const float4*)(base + (size_t)j * C_ + lane * 4);
        m.x = fmaxf(m.x, v.x); m.y = fmaxf(m.y, v.y);
        m.z = fmaxf(m.z, v.z); m.w = fmaxf(m.w, v.w);
    }

    float p[OS_];
    #pragma unroll
    for (int o = 0; o < OS_; o++) {
        float4 wv = *(const float4*)(sW + o * C_ + lane * 4);
        p[o] = m.x * wv.x;
        p[o] = fmaf(m.y, wv.y, p[o]);
        p[o] = fmaf(m.z, wv.z, p[o]);
        p[o] = fmaf(m.w, wv.w, p[o]);
    }
    #pragma unroll
    for (int o = 0; o < OS_; o++)
        #pragma unroll
        for (int off = 16; off; off >>= 1)
            p[o] += __shfl_xor_sync(0xffffffffu, p[o], off);

    if (lane == 0) {
        #pragma unroll
        for (int o = 0; o < OS_; o++)
            p_out[((size_t)(b * OS_ + o)) * N_ + n] = p[o] + sb[o];
    }
}

// ============================================================================
extern "C" void kernel_launch(void* const* d_in, const int* in_sizes, int n_in,
                              void* d_out, int out_size)
{
    const float* f_sem   = (const float*)d_in[0];
    const float* f_ins   = (const float*)d_in[1];
    const float* W_adapt = (const float*)d_in[2];
    const float* b_adapt = (const float*)d_in[3];
    const float* gamma_a = (const float*)d_in[4];
    const float* beta_a  = (const float*)d_in[5];
    const float* W_ins   = (const float*)d_in[6];
    const float* b_ins   = (const float*)d_in[7];
    const float* W_sem   = (const float*)d_in[8];
    const float* b_sem   = (const float*)d_in[9];

    float* out   = (float*)d_out;
    float* p_out = out;                           // [B,13,N]
    float* e_out = out + (size_t)B_ * OS_ * N_;   // [B,5,N]

    const int smemA = (16384 + 16384 + 640 + 392) * (int)sizeof(float);  // ~135 KB
    const int smemC = N_ * 8 * (int)sizeof(float);                       // 128 KB
    cudaFuncSetAttribute(mlp_kernel, cudaFuncAttributeMaxDynamicSharedMemorySize, smemA);
    cudaFuncSetAttribute(knn_kernel, cudaFuncAttributeMaxDynamicSharedMemorySize, smemC);

    mlp_kernel<<<dim3(N_ / 128, B_), 256, smemA>>>(
        f_sem, f_ins, W_adapt, b_adapt, gamma_a, beta_a, W_ins, b_ins, e_out);
    transpose_kernel<<<dim3(N_ / 32, C_ / 32, B_), dim3(32, 8)>>>(f_sem);
    knn_kernel<<<dim3(N_ / 256, B_), 256, smemC>>>();
    gather_kernel<<<dim3(N_ / 8, B_), 256>>>(W_sem, b_sem, p_out);
}

// round 8
// speedup vs baseline: 1.0936x; 1.0936x over previous
#include <cuda_runtime.h>
#include <float.h>

#define B_  8
#define N_  4096
#define C_  128
#define OI_ 5
#define OS_ 13
#define K_  30
#define FULL 0xffffffffu

// ---- scratch (static device globals; no runtime allocation) ----
__device__ __align__(16) float g_epts[B_ * N_ * 8];            // [b][n][8]: e0..e4, sq, pad
__device__ __align__(16) float g_fsemT[(size_t)B_ * N_ * C_];  // [b][n][c]
__device__ int g_nnidx[B_ * N_ * K_];                          // [b][n][k] (unordered set)

// Order-preserving float <-> u32 key (monotone over the entire float line,
// including negative distances such as rounded self-distances).
__device__ __forceinline__ unsigned f2o(float f) {
    unsigned u = __float_as_uint(f);
    return u ^ ((u & 0x80000000u) ? 0xFFFFFFFFu : 0x80000000u);
}
__device__ __forceinline__ float o2f(unsigned k) {
    k ^= (k & 0x80000000u) ? 0x80000000u : 0xFFFFFFFFu;
    return __uint_as_float(k);
}

// ============================================================================
// Kernel A: fused adaptation MLP + e_ins. (unchanged from passing R5 version)
// ============================================================================
__global__ void __launch_bounds__(256, 1)
mlp_kernel(const float* __restrict__ f_sem, const float* __restrict__ f_ins,
           const float* __restrict__ W_adapt, const float* __restrict__ b_adapt,
           const float* __restrict__ gamma_a, const float* __restrict__ beta_a,
           const float* __restrict__ W_ins, const float* __restrict__ b_ins,
           float* __restrict__ e_out)
{
    extern __shared__ float sm[];
    float* sW   = sm;            // 16384: W_adapt[c][s]
    float* sX   = sm + 16384;    // 16384: f_sem[s][n] tile, then f_sins[c][n]
    float* sWi  = sX + 16384;    // 640:   W_ins[o][c]
    float* sPar = sWi + 640;     // 392:   b_adapt | gamma | beta | b_ins

    const int t  = threadIdx.x;
    const int b  = blockIdx.y;
    const int n0 = blockIdx.x * 128;

    {
        const float4* W4 = (const float4*)W_adapt;
        float4* sW4 = (float4*)sW;
        #pragma unroll
        for (int i = 0; i < 16; i++) sW4[t + 256 * i] = W4[t + 256 * i];
    }
    for (int i4 = t; i4 < 4096; i4 += 256) {
        int s = i4 >> 5, nn = (i4 & 31) * 4;
        ((float4*)sX)[i4] = *(const float4*)(f_sem + ((size_t)(b * C_ + s)) * N_ + n0 + nn);
    }
    if (t < 128) { sPar[t] = b_adapt[t]; sPar[128 + t] = gamma_a[t]; sPar[256 + t] = beta_a[t]; }
    else if (t < 133) sPar[384 + (t - 128)] = b_ins[t - 128];
    for (int i = t; i < 640; i += 256) sWi[i] = W_ins[i];
    __syncthreads();

    const int tx = t & 15, ty = t >> 4;
    const int c0 = ty * 8, nl = tx * 8;
    float acc[8][8];
    #pragma unroll
    for (int u = 0; u < 8; u++)
        #pragma unroll
        for (int v = 0; v < 8; v++) acc[u][v] = 0.f;

    for (int s = 0; s < 128; s++) {
        float a[8];
        #pragma unroll
        for (int u = 0; u < 8; u++) a[u] = sW[(c0 + u) * 128 + s];
        float4 p0 = *(float4*)(sX + s * 128 + nl);
        float4 p1 = *(float4*)(sX + s * 128 + nl + 4);
        float bb[8] = {p0.x, p0.y, p0.z, p0.w, p1.x, p1.y, p1.z, p1.w};
        #pragma unroll
        for (int u = 0; u < 8; u++)
            #pragma unroll
            for (int v = 0; v < 8; v++) acc[u][v] = fmaf(a[u], bb[v], acc[u][v]);
    }
    __syncthreads();  // all reads of sX done before overwrite

    #pragma unroll
    for (int u = 0; u < 8; u++) {
        int c = c0 + u;
        float ba = sPar[c], ga = sPar[128 + c], be = sPar[256 + c];
        const float* fip = f_ins + ((size_t)(b * C_ + c)) * N_ + n0 + nl;
        float4 f0 = *(const float4*)fip;
        float4 f1 = *(const float4*)(fip + 4);
        float fv[8] = {f0.x, f0.y, f0.z, f0.w, f1.x, f1.y, f1.z, f1.w};
        #pragma unroll
        for (int v = 0; v < 8; v++) {
            float val = fmaf(ga, acc[u][v] + ba, be);
            val = fmaxf(val, 0.f) + fv[v];
            sX[c * 128 + nl + v] = val;   // f_sins
        }
    }
    __syncthreads();

    if (t < 128) {
        int n = n0 + t;
        float a0 = sPar[384], a1 = sPar[385], a2 = sPar[386], a3 = sPar[387], a4 = sPar[388];
        for (int c = 0; c < 128; c++) {
            float f = sX[c * 128 + t];
            a0 = fmaf(sWi[c], f, a0);
            a1 = fmaf(sWi[128 + c], f, a1);
            a2 = fmaf(sWi[256 + c], f, a2);
            a3 = fmaf(sWi[384 + c], f, a3);
            a4 = fmaf(sWi[512 + c], f, a4);
        }
        // sq exactly as reference: per-element rounded square, sequential add.
        float s0 = __fmul_rn(a0, a0);
        float s1 = __fmul_rn(a1, a1);
        float s2 = __fmul_rn(a2, a2);
        float s3 = __fmul_rn(a3, a3);
        float s4 = __fmul_rn(a4, a4);
        float sq = __fadd_rn(__fadd_rn(__fadd_rn(__fadd_rn(s0, s1), s2), s3), s4);
        size_t ob = (size_t)b * OI_ * N_ + n;
        e_out[ob] = a0; e_out[ob + N_] = a1; e_out[ob + 2 * N_] = a2;
        e_out[ob + 3 * N_] = a3; e_out[ob + 4 * N_] = a4;
        float* ep = g_epts + ((size_t)b * N_ + n) * 8;
        ep[0] = a0; ep[1] = a1; ep[2] = a2; ep[3] = a3; ep[4] = a4;
        ep[5] = sq; ep[6] = 0.f; ep[7] = 0.f;
    }
}

// ============================================================================
// Kernel B: transpose f_sem [B,C,N] -> g_fsemT [B,N,C]. (unchanged)
// ============================================================================
__global__ void __launch_bounds__(256, 2)
transpose_kernel(const float* __restrict__ f_sem)
{
    __shared__ float tile[32][33];
    const int b = blockIdx.z, c0 = blockIdx.y * 32, x0 = blockIdx.x * 32;
    const int tx = threadIdx.x, ty = threadIdx.y;  // 32 x 8
    #pragma unroll
    for (int j = 0; j < 32; j += 8)
        tile[ty + j][tx] = f_sem[((size_t)(b * C_ + c0 + ty + j)) * N_ + x0 + tx];
    __syncthreads();
    #pragma unroll
    for (int j = 0; j < 32; j += 8)
        g_fsemT[((size_t)b * N_ + x0 + ty + j) * C_ + c0 + tx] = tile[tx][ty + j];
}

// ============================================================================
// Kernel C: exact 30-NN, WARP-PER-QUERY.
// Top-30 distributed across lanes 0..29 (one (key,idx) per lane), where key is
// the order-preserving u32 mapping of the distance (handles negative
// distances, e.g. rounded self-distance). Per iteration each lane computes one
// candidate distance; ballot finds those beating the current worst; accepted
// candidates are applied one at a time with uniform control flow: predicated
// replace at the tracked max-lane, REDUX.MAX on keys + ballot + ffs recomputes
// (worst, wslot). Duplicate-worst ties evict the larger index (rare path),
// matching jax top_k's lower-index preference; ascending-j processing with
// strict '<' handles incoming ties. Distance rounding order is bit-identical
// to the reference.
// ============================================================================
#define KNN_WARPS 8
#define QPW 4

__global__ void __launch_bounds__(256, 2)
knn_kernel()
{
    extern __shared__ float sm[];
    float4* sc4 = (float4*)sm;               // [4096] e0..e3   (64 KB)
    float2* sc2 = (float2*)(sm + 4 * N_);    // [4096] e4, sq   (32 KB)

    const int t = threadIdx.x, b = blockIdx.y;
    {
        const float4* eb = (const float4*)(g_epts + (size_t)b * N_ * 8);
        for (int i = t; i < N_; i += 256) {
            float4 a = eb[2 * i];
            float4 c = eb[2 * i + 1];
            sc4[i] = a;
            sc2[i] = make_float2(c.x, c.y);
        }
    }
    __syncthreads();

    const int w = t >> 5, lane = t & 31;
    const unsigned lane_bit = 1u << lane;
    const unsigned MASK30 = (1u << K_) - 1u;

    for (int qi = 0; qi < QPW; qi++) {
        const int q = (blockIdx.x * KNN_WARPS + w) * QPW + qi;
        float4 qa = sc4[q];
        float2 qb = sc2[q];
        const float e0 = qa.x, e1 = qa.y, e2 = qa.z, e3 = qa.w;
        const float e4 = qb.x, sqi = qb.y;

        // lane-distributed top-30: lanes >= 30 hold key 0 (below every real key)
        unsigned bdk = (lane < K_) ? f2o(FLT_MAX) : 0u;
        int bi = 0x7FFFFFFF;
        float worst = FLT_MAX;
        int wslot = 0;

        for (int i = 0; i < N_ / 32; i++) {
            const int j = i * 32 + lane;
            float4 cv = sc4[j];
            float2 c2 = sc2[j];
            float dot = __fmul_rn(e0, cv.x);
            dot = __fmaf_rn(e1, cv.y, dot);
            dot = __fmaf_rn(e2, cv.z, dot);
            dot = __fmaf_rn(e3, cv.w, dot);
            dot = __fmaf_rn(e4, c2.x, dot);
            float d = __fadd_rn(__fsub_rn(sqi, __fmul_rn(2.0f, dot)), c2.y);

            unsigned hit = __ballot_sync(FULL, d < worst);
            while (hit) {
                const int src = __ffs(hit) - 1;
                hit &= hit - 1;
                const float dc = __shfl_sync(FULL, d, src);
                if (dc < worst) {
                    const int jc = i * 32 + src;
                    if (lane == wslot) { bdk = f2o(dc); bi = jc; }
                    const unsigned wk = __reduce_max_sync(FULL, bdk);
                    const unsigned em = __ballot_sync(FULL, bdk == wk) & MASK30;
                    if (__popc(em) == 1) {
                        wslot = __ffs(em) - 1;
                    } else {
                        // rare: duplicate distances at the boundary — evict larger index
                        const int key = (em & lane_bit) ? bi : (int)0x80000000;
                        const int mb = __reduce_max_sync(FULL, key);
                        const unsigned em2 = __ballot_sync(FULL, key == mb);
                        wslot = __ffs(em2) - 1;
                    }
                    worst = o2f(wk);
                }
            }
        }

        if (lane < K_)
            g_nnidx[((size_t)b * N_ + q) * K_ + lane] = bi;
    }
}

// ============================================================================
// Kernel D: f_isem = max_k f_sem[:, nn_idx[n,k]]; p_sem = W_sem @ f_isem + b.
// (unchanged; order-independent max so unordered nn sets are fine)
// ============================================================================
__global__ void __launch_bounds__(256, 2)
gather_kernel(const float* __restrict__ W_sem, const float* __restrict__ b_sem,
              float* __restrict__ p_out)
{
    __shared__ __align__(16) float sW[OS_ * C_];
    __shared__ float sb[OS_];
    const int t = threadIdx.x, b = blockIdx.y;
    for (int i = t; i < OS_ * C_; i += 256) sW[i] = W_sem[i];
    if (t < OS_) sb[t] = b_sem[t];
    __syncthreads();

    const int w = t >> 5, lane = t & 31;
    const int n = blockIdx.x * 8 + w;
    const int* ip = g_nnidx + ((size_t)b * N_ + n) * K_;
    int myidx = (lane < K_) ? ip[lane] : 0;
    const float* base = g_fsemT + (size_t)b * N_ * C_;

    float4 m = make_float4(-3.0e38f, -3.0e38f, -3.0e38f, -3.0e38f);
    #pragma unroll
    for (int k = 0; k < K_; k++) {
        int j = __shfl_sync(FULL, myidx, k);
        float4 v = *(const float4*)(base + (size_t)j * C_ + lane * 4);
        m.x = fmaxf(m.x, v.x); m.y = fmaxf(m.y, v.y);
        m.z = fmaxf(m.z, v.z); m.w = fmaxf(m.w, v.w);
    }

    float p[OS_];
    #pragma unroll
    for (int o = 0; o < OS_; o++) {
        float4 wv = *(const float4*)(sW + o * C_ + lane * 4);
        p[o] = m.x * wv.x;
        p[o] = fmaf(m.y, wv.y, p[o]);
        p[o] = fmaf(m.z, wv.z, p[o]);
        p[o] = fmaf(m.w, wv.w, p[o]);
    }
    #pragma unroll
    for (int o = 0; o < OS_; o++)
        #pragma unroll
        for (int off = 16; off; off >>= 1)
            p[o] += __shfl_xor_sync(FULL, p[o], off);

    if (lane == 0) {
        #pragma unroll
        for (int o = 0; o < OS_; o++)
            p_out[((size_t)(b * OS_ + o)) * N_ + n] = p[o] + sb[o];
    }
}

// ============================================================================
extern "C" void kernel_launch(void* const* d_in, const int* in_sizes, int n_in,
                              void* d_out, int out_size)
{
    const float* f_sem   = (const float*)d_in[0];
    const float* f_ins   = (const float*)d_in[1];
    const float* W_adapt = (const float*)d_in[2];
    const float* b_adapt = (const float*)d_in[3];
    const float* gamma_a = (const float*)d_in[4];
    const float* beta_a  = (const float*)d_in[5];
    const float* W_ins   = (const float*)d_in[6];
    const float* b_ins   = (const float*)d_in[7];
    const float* W_sem   = (const float*)d_in[8];
    const float* b_sem   = (const float*)d_in[9];

    float* out   = (float*)d_out;
    float* p_out = out;                           // [B,13,N]
    float* e_out = out + (size_t)B_ * OS_ * N_;   // [B,5,N]

    const int smemA = (16384 + 16384 + 640 + 392) * (int)sizeof(float);  // ~135 KB
    const int smemC = N_ * 6 * (int)sizeof(float);                       // 96 KB
    cudaFuncSetAttribute(mlp_kernel, cudaFuncAttributeMaxDynamicSharedMemorySize, smemA);
    cudaFuncSetAttribute(knn_kernel, cudaFuncAttributeMaxDynamicSharedMemorySize, smemC);

    mlp_kernel<<<dim3(N_ / 128, B_), 256, smemA>>>(
        f_sem, f_ins, W_adapt, b_adapt, gamma_a, beta_a, W_ins, b_ins, e_out);
    transpose_kernel<<<dim3(N_ / 32, C_ / 32, B_), dim3(32, 8)>>>(f_sem);
    knn_kernel<<<dim3(N_ / (KNN_WARPS * QPW), B_), 256, smemC>>>();
    gather_kernel<<<dim3(N_ / 8, B_), 256>>>(W_sem, b_sem, p_out);
}

// round 9
// speedup vs baseline: 1.6389x; 1.4986x over previous
#include <cuda_runtime.h>
#include <float.h>

#define B_  8
#define N_  4096
#define C_  128
#define OI_ 5
#define OS_ 13
#define K_  30
#define FULL 0xffffffffu

// ---- scratch (static device globals; no runtime allocation) ----
__device__ __align__(16) float g_epts[B_ * N_ * 8];            // [b][n][8]: e0..e4, sq, pad
__device__ __align__(16) float g_fsemT[(size_t)B_ * N_ * C_];  // [b][n][c]
__device__ int g_nnidx[B_ * N_ * K_];                          // [b][n][k] (unordered set)

// Order-preserving float <-> u32 key (monotone over the entire float line,
// including negative distances such as rounded self-distances).
__device__ __forceinline__ unsigned f2o(float f) {
    unsigned u = __float_as_uint(f);
    return u ^ ((u & 0x80000000u) ? 0xFFFFFFFFu : 0x80000000u);
}
__device__ __forceinline__ float o2f(unsigned k) {
    k ^= (k & 0x80000000u) ? 0x80000000u : 0xFFFFFFFFu;
    return __uint_as_float(k);
}

// ============================================================================
// Kernel A: fused adaptation MLP + e_ins. (unchanged from passing version)
// ============================================================================
__global__ void __launch_bounds__(256, 1)
mlp_kernel(const float* __restrict__ f_sem, const float* __restrict__ f_ins,
           const float* __restrict__ W_adapt, const float* __restrict__ b_adapt,
           const float* __restrict__ gamma_a, const float* __restrict__ beta_a,
           const float* __restrict__ W_ins, const float* __restrict__ b_ins,
           float* __restrict__ e_out)
{
    extern __shared__ float sm[];
    float* sW   = sm;            // 16384: W_adapt[c][s]
    float* sX   = sm + 16384;    // 16384: f_sem[s][n] tile, then f_sins[c][n]
    float* sWi  = sX + 16384;    // 640:   W_ins[o][c]
    float* sPar = sWi + 640;     // 392:   b_adapt | gamma | beta | b_ins

    const int t  = threadIdx.x;
    const int b  = blockIdx.y;
    const int n0 = blockIdx.x * 128;

    {
        const float4* W4 = (const float4*)W_adapt;
        float4* sW4 = (float4*)sW;
        #pragma unroll
        for (int i = 0; i < 16; i++) sW4[t + 256 * i] = W4[t + 256 * i];
    }
    for (int i4 = t; i4 < 4096; i4 += 256) {
        int s = i4 >> 5, nn = (i4 & 31) * 4;
        ((float4*)sX)[i4] = *(const float4*)(f_sem + ((size_t)(b * C_ + s)) * N_ + n0 + nn);
    }
    if (t < 128) { sPar[t] = b_adapt[t]; sPar[128 + t] = gamma_a[t]; sPar[256 + t] = beta_a[t]; }
    else if (t < 133) sPar[384 + (t - 128)] = b_ins[t - 128];
    for (int i = t; i < 640; i += 256) sWi[i] = W_ins[i];
    __syncthreads();

    const int tx = t & 15, ty = t >> 4;
    const int c0 = ty * 8, nl = tx * 8;
    float acc[8][8];
    #pragma unroll
    for (int u = 0; u < 8; u++)
        #pragma unroll
        for (int v = 0; v < 8; v++) acc[u][v] = 0.f;

    for (int s = 0; s < 128; s++) {
        float a[8];
        #pragma unroll
        for (int u = 0; u < 8; u++) a[u] = sW[(c0 + u) * 128 + s];
        float4 p0 = *(float4*)(sX + s * 128 + nl);
        float4 p1 = *(float4*)(sX + s * 128 + nl + 4);
        float bb[8] = {p0.x, p0.y, p0.z, p0.w, p1.x, p1.y, p1.z, p1.w};
        #pragma unroll
        for (int u = 0; u < 8; u++)
            #pragma unroll
            for (int v = 0; v < 8; v++) acc[u][v] = fmaf(a[u], bb[v], acc[u][v]);
    }
    __syncthreads();  // all reads of sX done before overwrite

    #pragma unroll
    for (int u = 0; u < 8; u++) {
        int c = c0 + u;
        float ba = sPar[c], ga = sPar[128 + c], be = sPar[256 + c];
        const float* fip = f_ins + ((size_t)(b * C_ + c)) * N_ + n0 + nl;
        float4 f0 = *(const float4*)fip;
        float4 f1 = *(const float4*)(fip + 4);
        float fv[8] = {f0.x, f0.y, f0.z, f0.w, f1.x, f1.y, f1.z, f1.w};
        #pragma unroll
        for (int v = 0; v < 8; v++) {
            float val = fmaf(ga, acc[u][v] + ba, be);
            val = fmaxf(val, 0.f) + fv[v];
            sX[c * 128 + nl + v] = val;   // f_sins
        }
    }
    __syncthreads();

    if (t < 128) {
        int n = n0 + t;
        float a0 = sPar[384], a1 = sPar[385], a2 = sPar[386], a3 = sPar[387], a4 = sPar[388];
        for (int c = 0; c < 128; c++) {
            float f = sX[c * 128 + t];
            a0 = fmaf(sWi[c], f, a0);
            a1 = fmaf(sWi[128 + c], f, a1);
            a2 = fmaf(sWi[256 + c], f, a2);
            a3 = fmaf(sWi[384 + c], f, a3);
            a4 = fmaf(sWi[512 + c], f, a4);
        }
        // sq exactly as reference: per-element rounded square, sequential add.
        float s0 = __fmul_rn(a0, a0);
        float s1 = __fmul_rn(a1, a1);
        float s2 = __fmul_rn(a2, a2);
        float s3 = __fmul_rn(a3, a3);
        float s4 = __fmul_rn(a4, a4);
        float sq = __fadd_rn(__fadd_rn(__fadd_rn(__fadd_rn(s0, s1), s2), s3), s4);
        size_t ob = (size_t)b * OI_ * N_ + n;
        e_out[ob] = a0; e_out[ob + N_] = a1; e_out[ob + 2 * N_] = a2;
        e_out[ob + 3 * N_] = a3; e_out[ob + 4 * N_] = a4;
        float* ep = g_epts + ((size_t)b * N_ + n) * 8;
        ep[0] = a0; ep[1] = a1; ep[2] = a2; ep[3] = a3; ep[4] = a4;
        ep[5] = sq; ep[6] = 0.f; ep[7] = 0.f;
    }
}

// ============================================================================
// Kernel B: transpose f_sem [B,C,N] -> g_fsemT [B,N,C]. (unchanged)
// ============================================================================
__global__ void __launch_bounds__(256, 2)
transpose_kernel(const float* __restrict__ f_sem)
{
    __shared__ float tile[32][33];
    const int b = blockIdx.z, c0 = blockIdx.y * 32, x0 = blockIdx.x * 32;
    const int tx = threadIdx.x, ty = threadIdx.y;  // 32 x 8
    #pragma unroll
    for (int j = 0; j < 32; j += 8)
        tile[ty + j][tx] = f_sem[((size_t)(b * C_ + c0 + ty + j)) * N_ + x0 + tx];
    __syncthreads();
    #pragma unroll
    for (int j = 0; j < 32; j += 8)
        g_fsemT[((size_t)b * N_ + x0 + ty + j) * C_ + c0 + tx] = tile[tx][ty + j];
}

// ============================================================================
// Kernel C: exact 30-NN, WARP-PER-QUERY. Selection machinery identical to the
// passing version; only the launch shape changed: 512-thread blocks (16 warps)
// x 2 queries/warp, __launch_bounds__(512,2) so two blocks (2x96KB smem fits)
// are resident -> 32 warps/SM, doubling latency hiding for the serially-
// dependent insert chains (shfl -> REDUX -> ballot).
// ============================================================================
#define KNN_THREADS 512
#define KNN_WARPS  (KNN_THREADS / 32)
#define QPW 2

__global__ void __launch_bounds__(KNN_THREADS, 2)
knn_kernel()
{
    extern __shared__ float smk[];
    float4* sc4 = (float4*)smk;               // [4096] e0..e3   (64 KB)
    float2* sc2 = (float2*)(smk + 4 * N_);    // [4096] e4, sq   (32 KB)

    const int t = threadIdx.x, b = blockIdx.y;
    {
        const float4* eb = (const float4*)(g_epts + (size_t)b * N_ * 8);
        for (int i = t; i < N_; i += KNN_THREADS) {
            float4 a = eb[2 * i];
            float4 c = eb[2 * i + 1];
            sc4[i] = a;
            sc2[i] = make_float2(c.x, c.y);
        }
    }
    __syncthreads();

    const int w = t >> 5, lane = t & 31;
    const unsigned lane_bit = 1u << lane;
    const unsigned MASK30 = (1u << K_) - 1u;

    for (int qi = 0; qi < QPW; qi++) {
        const int q = (blockIdx.x * KNN_WARPS + w) * QPW + qi;
        float4 qa = sc4[q];
        float2 qb = sc2[q];
        const float e0 = qa.x, e1 = qa.y, e2 = qa.z, e3 = qa.w;
        const float e4 = qb.x, sqi = qb.y;

        // lane-distributed top-30: lanes >= 30 hold key 0 (below every real key)
        unsigned bdk = (lane < K_) ? f2o(FLT_MAX) : 0u;
        int bi = 0x7FFFFFFF;
        float worst = FLT_MAX;
        int wslot = 0;

        for (int i = 0; i < N_ / 32; i++) {
            const int j = i * 32 + lane;
            float4 cv = sc4[j];
            float2 c2 = sc2[j];
            float dot = __fmul_rn(e0, cv.x);
            dot = __fmaf_rn(e1, cv.y, dot);
            dot = __fmaf_rn(e2, cv.z, dot);
            dot = __fmaf_rn(e3, cv.w, dot);
            dot = __fmaf_rn(e4, c2.x, dot);
            float d = __fadd_rn(__fsub_rn(sqi, __fmul_rn(2.0f, dot)), c2.y);

            unsigned hit = __ballot_sync(FULL, d < worst);
            while (hit) {
                const int src = __ffs(hit) - 1;
                hit &= hit - 1;
                const float dc = __shfl_sync(FULL, d, src);
                if (dc < worst) {
                    const int jc = i * 32 + src;
                    if (lane == wslot) { bdk = f2o(dc); bi = jc; }
                    const unsigned wk = __reduce_max_sync(FULL, bdk);
                    const unsigned em = __ballot_sync(FULL, bdk == wk) & MASK30;
                    if (__popc(em) == 1) {
                        wslot = __ffs(em) - 1;
                    } else {
                        // rare: duplicate distances at the boundary — evict larger index
                        const int key = (em & lane_bit) ? bi : (int)0x80000000;
                        const int mb = __reduce_max_sync(FULL, key);
                        const unsigned em2 = __ballot_sync(FULL, key == mb);
                        wslot = __ffs(em2) - 1;
                    }
                    worst = o2f(wk);
                }
            }
        }

        if (lane < K_)
            g_nnidx[((size_t)b * N_ + q) * K_ + lane] = bi;
    }
}

// ============================================================================
// Kernel D: f_isem = max_k f_sem[:, nn_idx[n,k]]; p_sem = W_sem @ f_isem + b.
// Same structure; __launch_bounds__(256,4) caps regs at 64 (was 128) to
// double occupancy on this L1-latency-bound kernel.
// ============================================================================
__global__ void __launch_bounds__(256, 4)
gather_kernel(const float* __restrict__ W_sem, const float* __restrict__ b_sem,
              float* __restrict__ p_out)
{
    __shared__ __align__(16) float sW[OS_ * C_];
    __shared__ float sb[OS_];
    const int t = threadIdx.x, b = blockIdx.y;
    for (int i = t; i < OS_ * C_; i += 256) sW[i] = W_sem[i];
    if (t < OS_) sb[t] = b_sem[t];
    __syncthreads();

    const int w = t >> 5, lane = t & 31;
    const int n = blockIdx.x * 8 + w;
    const int* ip = g_nnidx + ((size_t)b * N_ + n) * K_;
    int myidx = (lane < K_) ? ip[lane] : 0;
    const float* base = g_fsemT + (size_t)b * N_ * C_;

    float4 m = make_float4(-3.0e38f, -3.0e38f, -3.0e38f, -3.0e38f);
    #pragma unroll
    for (int k = 0; k < K_; k++) {
        int j = __shfl_sync(FULL, myidx, k);
        float4 v = *(const float4*)(base + (size_t)j * C_ + lane * 4);
        m.x = fmaxf(m.x, v.x); m.y = fmaxf(m.y, v.y);
        m.z = fmaxf(m.z, v.z); m.w = fmaxf(m.w, v.w);
    }

    float p[OS_];
    #pragma unroll
    for (int o = 0; o < OS_; o++) {
        float4 wv = *(const float4*)(sW + o * C_ + lane * 4);
        p[o] = m.x * wv.x;
        p[o] = fmaf(m.y, wv.y, p[o]);
        p[o] = fmaf(m.z, wv.z, p[o]);
        p[o] = fmaf(m.w, wv.w, p[o]);
    }
    #pragma unroll
    for (int o = 0; o < OS_; o++)
        #pragma unroll
        for (int off = 16; off; off >>= 1)
            p[o] += __shfl_xor_sync(FULL, p[o], off);

    if (lane == 0) {
        #pragma unroll
        for (int o = 0; o < OS_; o++)
            p_out[((size_t)(b * OS_ + o)) * N_ + n] = p[o] + sb[o];
    }
}

// ============================================================================
extern "C" void kernel_launch(void* const* d_in, const int* in_sizes, int n_in,
                              void* d_out, int out_size)
{
    const float* f_sem   = (const float*)d_in[0];
    const float* f_ins   = (const float*)d_in[1];
    const float* W_adapt = (const float*)d_in[2];
    const float* b_adapt = (const float*)d_in[3];
    const float* gamma_a = (const float*)d_in[4];
    const float* beta_a  = (const float*)d_in[5];
    const float* W_ins   = (const float*)d_in[6];
    const float* b_ins   = (const float*)d_in[7];
    const float* W_sem   = (const float*)d_in[8];
    const float* b_sem   = (const float*)d_in[9];

    float* out   = (float*)d_out;
    float* p_out = out;                           // [B,13,N]
    float* e_out = out + (size_t)B_ * OS_ * N_;   // [B,5,N]

    const int smemA = (16384 + 16384 + 640 + 392) * (int)sizeof(float);  // ~135 KB
    const int smemC = N_ * 6 * (int)sizeof(float);                       // 96 KB
    cudaFuncSetAttribute(mlp_kernel, cudaFuncAttributeMaxDynamicSharedMemorySize, smemA);
    cudaFuncSetAttribute(knn_kernel, cudaFuncAttributeMaxDynamicSharedMemorySize, smemC);

    mlp_kernel<<<dim3(N_ / 128, B_), 256, smemA>>>(
        f_sem, f_ins, W_adapt, b_adapt, gamma_a, beta_a, W_ins, b_ins, e_out);
    transpose_kernel<<<dim3(N_ / 32, C_ / 32, B_), dim3(32, 8)>>>(f_sem);
    knn_kernel<<<dim3(N_ / (KNN_WARPS * QPW), B_), KNN_THREADS, smemC>>>();
    gather_kernel<<<dim3(N_ / 8, B_), 256>>>(W_sem, b_sem, p_out);
}

// round 12
// speedup vs baseline: 2.0658x; 1.2604x over previous
#include <cuda_runtime.h>
#include <float.h>

#define B_  8
#define N_  4096
#define C_  128
#define OI_ 5
#define OS_ 13
#define K_  30
#define FULL 0xffffffffu

// ---- scratch (static device globals; no runtime allocation) ----
__device__ __align__(16) float g_epts[B_ * N_ * 8];            // [b][n][8]: e0..e4, sq, pad
__device__ __align__(16) float g_fsemT[(size_t)B_ * N_ * C_];  // [b][n][c]
__device__ int g_nnidx[B_ * N_ * K_];                          // [b][n][k] (unordered set)

// Order-preserving float <-> u32 key (monotone over the entire float line,
// including negative distances such as rounded self-distances).
__device__ __forceinline__ unsigned f2o(float f) {
    unsigned u = __float_as_uint(f);
    return u ^ ((u & 0x80000000u) ? 0xFFFFFFFFu : 0x80000000u);
}
__device__ __forceinline__ float o2f(unsigned k) {
    k ^= (k & 0x80000000u) ? 0x80000000u : 0xFFFFFFFFu;
    return __uint_as_float(k);
}

// ============================================================================
// Kernel A: fused adaptation MLP + e_ins. (unchanged from passing version)
// ============================================================================
__global__ void __launch_bounds__(256, 1)
mlp_kernel(const float* __restrict__ f_sem, const float* __restrict__ f_ins,
           const float* __restrict__ W_adapt, const float* __restrict__ b_adapt,
           const float* __restrict__ gamma_a, const float* __restrict__ beta_a,
           const float* __restrict__ W_ins, const float* __restrict__ b_ins,
           float* __restrict__ e_out)
{
    extern __shared__ float sm[];
    float* sW   = sm;            // 16384: W_adapt[c][s]
    float* sX   = sm + 16384;    // 16384: f_sem[s][n] tile, then f_sins[c][n]
    float* sWi  = sX + 16384;    // 640:   W_ins[o][c]
    float* sPar = sWi + 640;     // 392:   b_adapt | gamma | beta | b_ins

    const int t  = threadIdx.x;
    const int b  = blockIdx.y;
    const int n0 = blockIdx.x * 128;

    {
        const float4* W4 = (const float4*)W_adapt;
        float4* sW4 = (float4*)sW;
        #pragma unroll
        for (int i = 0; i < 16; i++) sW4[t + 256 * i] = W4[t + 256 * i];
    }
    for (int i4 = t; i4 < 4096; i4 += 256) {
        int s = i4 >> 5, nn = (i4 & 31) * 4;
        ((float4*)sX)[i4] = *(const float4*)(f_sem + ((size_t)(b * C_ + s)) * N_ + n0 + nn);
    }
    if (t < 128) { sPar[t] = b_adapt[t]; sPar[128 + t] = gamma_a[t]; sPar[256 + t] = beta_a[t]; }
    else if (t < 133) sPar[384 + (t - 128)] = b_ins[t - 128];
    for (int i = t; i < 640; i += 256) sWi[i] = W_ins[i];
    __syncthreads();

    const int tx = t & 15, ty = t >> 4;
    const int c0 = ty * 8, nl = tx * 8;
    float acc[8][8];
    #pragma unroll
    for (int u = 0; u < 8; u++)
        #pragma unroll
        for (int v = 0; v < 8; v++) acc[u][v] = 0.f;

    for (int s = 0; s < 128; s++) {
        float a[8];
        #pragma unroll
        for (int u = 0; u < 8; u++) a[u] = sW[(c0 + u) * 128 + s];
        float4 p0 = *(float4*)(sX + s * 128 + nl);
        float4 p1 = *(float4*)(sX + s * 128 + nl + 4);
        float bb[8] = {p0.x, p0.y, p0.z, p0.w, p1.x, p1.y, p1.z, p1.w};
        #pragma unroll
        for (int u = 0; u < 8; u++)
            #pragma unroll
            for (int v = 0; v < 8; v++) acc[u][v] = fmaf(a[u], bb[v], acc[u][v]);
    }
    __syncthreads();  // all reads of sX done before overwrite

    #pragma unroll
    for (int u = 0; u < 8; u++) {
        int c = c0 + u;
        float ba = sPar[c], ga = sPar[128 + c], be = sPar[256 + c];
        const float* fip = f_ins + ((size_t)(b * C_ + c)) * N_ + n0 + nl;
        float4 f0 = *(const float4*)fip;
        float4 f1 = *(const float4*)(fip + 4);
        float fv[8] = {f0.x, f0.y, f0.z, f0.w, f1.x, f1.y, f1.z, f1.w};
        #pragma unroll
        for (int v = 0; v < 8; v++) {
            float val = fmaf(ga, acc[u][v] + ba, be);
            val = fmaxf(val, 0.f) + fv[v];
            sX[c * 128 + nl + v] = val;   // f_sins
        }
    }
    __syncthreads();

    if (t < 128) {
        int n = n0 + t;
        float a0 = sPar[384], a1 = sPar[385], a2 = sPar[386], a3 = sPar[387], a4 = sPar[388];
        for (int c = 0; c < 128; c++) {
            float f = sX[c * 128 + t];
            a0 = fmaf(sWi[c], f, a0);
            a1 = fmaf(sWi[128 + c], f, a1);
            a2 = fmaf(sWi[256 + c], f, a2);
            a3 = fmaf(sWi[384 + c], f, a3);
            a4 = fmaf(sWi[512 + c], f, a4);
        }
        // sq exactly as reference: per-element rounded square, sequential add.
        float s0 = __fmul_rn(a0, a0);
        float s1 = __fmul_rn(a1, a1);
        float s2 = __fmul_rn(a2, a2);
        float s3 = __fmul_rn(a3, a3);
        float s4 = __fmul_rn(a4, a4);
        float sq = __fadd_rn(__fadd_rn(__fadd_rn(__fadd_rn(s0, s1), s2), s3), s4);
        size_t ob = (size_t)b * OI_ * N_ + n;
        e_out[ob] = a0; e_out[ob + N_] = a1; e_out[ob + 2 * N_] = a2;
        e_out[ob + 3 * N_] = a3; e_out[ob + 4 * N_] = a4;
        float* ep = g_epts + ((size_t)b * N_ + n) * 8;
        ep[0] = a0; ep[1] = a1; ep[2] = a2; ep[3] = a3; ep[4] = a4;
        ep[5] = sq; ep[6] = 0.f; ep[7] = 0.f;
    }
}

// ============================================================================
// Kernel B: transpose f_sem [B,C,N] -> g_fsemT [B,N,C]. (unchanged)
// ============================================================================
__global__ void __launch_bounds__(256, 2)
transpose_kernel(const float* __restrict__ f_sem)
{
    __shared__ float tile[32][33];
    const int b = blockIdx.z, c0 = blockIdx.y * 32, x0 = blockIdx.x * 32;
    const int tx = threadIdx.x, ty = threadIdx.y;  // 32 x 8
    #pragma unroll
    for (int j = 0; j < 32; j += 8)
        tile[ty + j][tx] = f_sem[((size_t)(b * C_ + c0 + ty + j)) * N_ + x0 + tx];
    __syncthreads();
    #pragma unroll
    for (int j = 0; j < 32; j += 8)
        g_fsemT[((size_t)b * N_ + x0 + ty + j) * C_ + c0 + tx] = tile[tx][ty + j];
}

// ============================================================================
// Kernel C: exact 30-NN, WARP-PER-QUERY.
// Changes vs the passing R9 version (selection SEMANTICS identical):
//  * 1024-thread blocks, __launch_bounds__(1024,2): 2 blocks x 1024 thr/SM =
//    64 resident warps (HW max) for this latency-bound kernel (smem 96KB x 2).
//  * Branchless insert chain: instead of tracking wslot + ballot + popc
//    branch, each lane tracks an is_evict flag. Per accepted candidate:
//    predicated replace at the evict lane -> REDUX.MAX on keys ->
//    REDUX.MAX on indices among worst-key holders -> is_evict=(ik==mb).
//    Kept indices are distinct (sentinels distinct per lane), so exactly one
//    lane matches. Eviction rule (largest index among duplicate-worst) and
//    ascending-j strict '<' are unchanged -> identical selected sets.
// ============================================================================
#define KNN_THREADS 1024
#define KNN_WARPS  (KNN_THREADS / 32)
#define QPW 1

__global__ void __launch_bounds__(KNN_THREADS, 2)
knn_kernel()
{
    extern __shared__ float smk[];
    float4* sc4 = (float4*)smk;               // [4096] e0..e3   (64 KB)
    float2* sc2 = (float2*)(smk + 4 * N_);    // [4096] e4, sq   (32 KB)

    const int t = threadIdx.x, b = blockIdx.y;
    {
        const float4* eb = (const float4*)(g_epts + (size_t)b * N_ * 8);
        for (int i = t; i < N_; i += KNN_THREADS) {
            float4 a = eb[2 * i];
            float4 c = eb[2 * i + 1];
            sc4[i] = a;
            sc2[i] = make_float2(c.x, c.y);
        }
    }
    __syncthreads();

    const int w = t >> 5, lane = t & 31;

    const int q = blockIdx.x * KNN_WARPS + w;
    float4 qa = sc4[q];
    float2 qb = sc2[q];
    const float e0 = qa.x, e1 = qa.y, e2 = qa.z, e3 = qa.w;
    const float e4 = qb.x, sqi = qb.y;

    // lane-distributed top-30: lanes >= 30 hold key 0 (below every real key).
    // Sentinel indices are distinct per lane and larger than any real j, so
    // during the fill phase the index-REDUX picks a unique evictee.
    unsigned bdk = (lane < K_) ? f2o(FLT_MAX) : 0u;
    int bi = 0x40000000 + lane;
    float worst = FLT_MAX;
    int is_evict = (lane == K_ - 1);

    for (int i = 0; i < N_ / 32; i++) {
        const int j = i * 32 + lane;
        float4 cv = sc4[j];
        float2 c2 = sc2[j];
        float dot = __fmul_rn(e0, cv.x);
        dot = __fmaf_rn(e1, cv.y, dot);
        dot = __fmaf_rn(e2, cv.z, dot);
        dot = __fmaf_rn(e3, cv.w, dot);
        dot = __fmaf_rn(e4, c2.x, dot);
        float d = __fadd_rn(__fsub_rn(sqi, __fmul_rn(2.0f, dot)), c2.y);

        unsigned hit = __ballot_sync(FULL, d < worst);
        while (hit) {
            const int src = __ffs(hit) - 1;
            hit &= hit - 1;
            const float dc = __shfl_sync(FULL, d, src);
            if (dc < worst) {
                const int jc = i * 32 + src;
                if (is_evict) { bdk = f2o(dc); bi = jc; }
                const unsigned wk = __reduce_max_sync(FULL, bdk);
                const int ik = (bdk == wk) ? bi : -1;     // lanes>=30: bdk=0 != wk
                const int mb = __reduce_max_sync(FULL, ik);
                is_evict = (ik == mb);                     // exactly one lane
                worst = o2f(wk);
            }
        }
    }

    if (lane < K_)
        g_nnidx[((size_t)b * N_ + q) * K_ + lane] = bi;
}

// ============================================================================
// Kernel D: f_isem = max_k f_sem[:, nn_idx[n,k]]; p_sem = W_sem @ f_isem + b.
// (unchanged from R9)
// ============================================================================
__global__ void __launch_bounds__(256, 4)
gather_kernel(const float* __restrict__ W_sem, const float* __restrict__ b_sem,
              float* __restrict__ p_out)
{
    __shared__ __align__(16) float sW[OS_ * C_];
    __shared__ float sb[OS_];
    const int t = threadIdx.x, b = blockIdx.y;
    for (int i = t; i < OS_ * C_; i += 256) sW[i] = W_sem[i];
    if (t < OS_) sb[t] = b_sem[t];
    __syncthreads();

    const int w = t >> 5, lane = t & 31;
    const int n = blockIdx.x * 8 + w;
    const int* ip = g_nnidx + ((size_t)b * N_ + n) * K_;
    int myidx = (lane < K_) ? ip[lane] : 0;
    const float* base = g_fsemT + (size_t)b * N_ * C_;

    float4 m = make_float4(-3.0e38f, -3.0e38f, -3.0e38f, -3.0e38f);
    #pragma unroll
    for (int k = 0; k < K_; k++) {
        int j = __shfl_sync(FULL, myidx, k);
        float4 v = *(const float4*)(base + (size_t)j * C_ + lane * 4);
        m.x = fmaxf(m.x, v.x); m.y = fmaxf(m.y, v.y);
        m.z = fmaxf(m.z, v.z); m.w = fmaxf(m.w, v.w);
    }

    float p[OS_];
    #pragma unroll
    for (int o = 0; o < OS_; o++) {
        float4 wv = *(const float4*)(sW + o * C_ + lane * 4);
        p[o] = m.x * wv.x;
        p[o] = fmaf(m.y, wv.y, p[o]);
        p[o] = fmaf(m.z, wv.z, p[o]);
        p[o] = fmaf(m.w, wv.w, p[o]);
    }
    #pragma unroll
    for (int o = 0; o < OS_; o++)
        #pragma unroll
        for (int off = 16; off; off >>= 1)
            p[o] += __shfl_xor_sync(FULL, p[o], off);

    if (lane == 0) {
        #pragma unroll
        for (int o = 0; o < OS_; o++)
            p_out[((size_t)(b * OS_ + o)) * N_ + n] = p[o] + sb[o];
    }
}

// ============================================================================
extern "C" void kernel_launch(void* const* d_in, const int* in_sizes, int n_in,
                              void* d_out, int out_size)
{
    const float* f_sem   = (const float*)d_in[0];
    const float* f_ins   = (const float*)d_in[1];
    const float* W_adapt = (const float*)d_in[2];
    const float* b_adapt = (const float*)d_in[3];
    const float* gamma_a = (const float*)d_in[4];
    const float* beta_a  = (const float*)d_in[5];
    const float* W_ins   = (const float*)d_in[6];
    const float* b_ins   = (const float*)d_in[7];
    const float* W_sem   = (const float*)d_in[8];
    const float* b_sem   = (const float*)d_in[9];

    float* out   = (float*)d_out;
    float* p_out = out;                           // [B,13,N]
    float* e_out = out + (size_t)B_ * OS_ * N_;   // [B,5,N]

    const int smemA = (16384 + 16384 + 640 + 392) * (int)sizeof(float);  // ~135 KB
    const int smemC = N_ * 6 * (int)sizeof(float);                       // 96 KB
    cudaFuncSetAttribute(mlp_kernel, cudaFuncAttributeMaxDynamicSharedMemorySize, smemA);
    cudaFuncSetAttribute(knn_kernel, cudaFuncAttributeMaxDynamicSharedMemorySize, smemC);

    mlp_kernel<<<dim3(N_ / 128, B_), 256, smemA>>>(
        f_sem, f_ins, W_adapt, b_adapt, gamma_a, beta_a, W_ins, b_ins, e_out);
    transpose_kernel<<<dim3(N_ / 32, C_ / 32, B_), dim3(32, 8)>>>(f_sem);
    knn_kernel<<<dim3(N_ / (KNN_WARPS * QPW), B_), KNN_THREADS, smemC>>>();
    gather_kernel<<<dim3(N_ / 8, B_), 256>>>(W_sem, b_sem, p_out);
}